// round 8
// baseline (speedup 1.0000x reference)
#include <cuda_runtime.h>
#include <math.h>

#define SEQ 4096
#define HID 1024
#define FH  4096   // 4*HID
#define NB  128    // scan blocks

// Scratch (no cudaMalloc allowed)
__device__ float g_xg[(size_t)SEQ * FH];
// h exchange: (float value, uint32 tag) packed in one 64-bit word, double-buffered.
// tag for h produced at step t is (t+1); zero = invalid.
__device__ unsigned long long g_hpair[2][HID];

// ---------------- packed f32x2 helpers (sm_103a) ----------------
__device__ __forceinline__ unsigned long long pk2(float x, float y) {
    unsigned long long r;
    asm("mov.b64 %0, {%1, %2};" : "=l"(r) : "f"(x), "f"(y));
    return r;
}
__device__ __forceinline__ void upk2(unsigned long long v, float& x, float& y) {
    asm("mov.b64 {%0, %1}, %2;" : "=f"(x), "=f"(y) : "l"(v));
}
__device__ __forceinline__ unsigned long long fma2(
    unsigned long long a, unsigned long long b, unsigned long long c) {
    unsigned long long d;
    asm("fma.rn.f32x2 %0, %1, %2, %3;" : "=l"(d) : "l"(a), "l"(b), "l"(c));
    return d;
}

// ---------------------------------------------------------------------------
// Kernel A: xg[s][r] = dot(emb[tok[s]], W_ih[r]) + b_ih[r] + b_hh[r]
// ---------------------------------------------------------------------------
__global__ __launch_bounds__(256) void xg_gemm(
    const int* __restrict__ tok, const float* __restrict__ emb,
    const float* __restrict__ Wih, const float* __restrict__ bih,
    const float* __restrict__ bhh)
{
    __shared__ float As[2][8][128];
    __shared__ float Bs[2][8][128];
    __shared__ int toks[128];

    const int tid = threadIdx.x;
    const int tx = tid & 15, ty = tid >> 4;
    const int s0 = blockIdx.y * 128;
    const int r0 = blockIdx.x * 128;

    if (tid < 128) toks[tid] = tok[s0 + tid];
    __syncthreads();

    unsigned long long acc2[8][4];
#pragma unroll
    for (int i = 0; i < 8; i++)
#pragma unroll
        for (int jp = 0; jp < 4; jp++) acc2[i][jp] = pk2(0.f, 0.f);

    const int lrow = tid >> 1;
    const int kq = (tid & 1) * 4;
    const size_t arow = (size_t)toks[lrow] * HID + kq;
    const size_t brow = (size_t)(r0 + lrow) * HID + kq;

    float4 av = *(const float4*)(emb + arow);
    float4 bv = *(const float4*)(Wih + brow);

    int buf = 0;
    for (int k0 = 0; k0 < HID; k0 += 8) {
        As[buf][kq + 0][lrow] = av.x; As[buf][kq + 1][lrow] = av.y;
        As[buf][kq + 2][lrow] = av.z; As[buf][kq + 3][lrow] = av.w;
        Bs[buf][kq + 0][lrow] = bv.x; Bs[buf][kq + 1][lrow] = bv.y;
        Bs[buf][kq + 2][lrow] = bv.z; Bs[buf][kq + 3][lrow] = bv.w;
        __syncthreads();
        if (k0 + 8 < HID) {
            av = *(const float4*)(emb + arow + k0 + 8);
            bv = *(const float4*)(Wih + brow + k0 + 8);
        }
#pragma unroll
        for (int kk = 0; kk < 8; kk++) {
            float4 alo = *(const float4*)&As[buf][kk][ty * 4];
            float4 ahi = *(const float4*)&As[buf][kk][64 + ty * 4];
            float4 blo = *(const float4*)&Bs[buf][kk][tx * 4];
            float4 bhi = *(const float4*)&Bs[buf][kk][64 + tx * 4];
            unsigned long long b2[4] = {
                pk2(blo.x, blo.y), pk2(blo.z, blo.w),
                pk2(bhi.x, bhi.y), pk2(bhi.z, bhi.w)};
            float a[8] = {alo.x, alo.y, alo.z, alo.w,
                          ahi.x, ahi.y, ahi.z, ahi.w};
#pragma unroll
            for (int i = 0; i < 8; i++) {
                unsigned long long ad = pk2(a[i], a[i]);
#pragma unroll
                for (int jp = 0; jp < 4; jp++)
                    acc2[i][jp] = fma2(ad, b2[jp], acc2[i][jp]);
            }
        }
        buf ^= 1;
    }

    float4 bl1 = *(const float4*)(bih + r0 + tx * 4);
    float4 bl2 = *(const float4*)(bhh + r0 + tx * 4);
    float4 bh1 = *(const float4*)(bih + r0 + 64 + tx * 4);
    float4 bh2 = *(const float4*)(bhh + r0 + 64 + tx * 4);
    float4 biasl = {bl1.x + bl2.x, bl1.y + bl2.y, bl1.z + bl2.z, bl1.w + bl2.w};
    float4 biash = {bh1.x + bh2.x, bh1.y + bh2.y, bh1.z + bh2.z, bh1.w + bh2.w};

#pragma unroll
    for (int i = 0; i < 8; i++) {
        int s = s0 + ((i < 4) ? (ty * 4 + i) : (64 + ty * 4 + i - 4));
        float4 o1, o2;
        upk2(acc2[i][0], o1.x, o1.y); upk2(acc2[i][1], o1.z, o1.w);
        upk2(acc2[i][2], o2.x, o2.y); upk2(acc2[i][3], o2.z, o2.w);
        o1.x += biasl.x; o1.y += biasl.y; o1.z += biasl.z; o1.w += biasl.w;
        o2.x += biash.x; o2.y += biash.y; o2.z += biash.z; o2.w += biash.w;
        *(float4*)(g_xg + (size_t)s * FH + r0 + tx * 4) = o1;
        *(float4*)(g_xg + (size_t)s * FH + r0 + 64 + tx * 4) = o2;
    }
}

// ---------------------------------------------------------------------------
// Kernel B: persistent 128-CTA scan, 256 threads, one warp per unit.
// h published as (value, tag) 64-bit words; consumers POLL THE DATA directly
// (no flags, no fences, no trailing barrier). Double-buffered on t&1.
// ---------------------------------------------------------------------------
__global__ __launch_bounds__(256, 1) void lstm_scan(
    const float* __restrict__ Whh, const float* __restrict__ h0,
    const float* __restrict__ c0)
{
    __shared__ float sh[32][33];     // h staged: h[k] at sh[k&31][k>>5]
    const int tid  = threadIdx.x;
    const int wid  = tid >> 5;       // unit within block (0..7)
    const int lane = tid & 31;
    const int j    = blockIdx.x * 8 + wid;

    // Preload W_hh rows {i,f,g,o} for unit j, k in [lane*32, lane*32+32)
    unsigned long long w2[4][16];
#pragma unroll
    for (int gate = 0; gate < 4; gate++) {
        const float4* p =
            (const float4*)(Whh + ((size_t)(gate * HID + j)) * HID + lane * 32);
#pragma unroll
        for (int q = 0; q < 8; q++) {
            float4 v = __ldg(p + q);
            w2[gate][2 * q + 0] = pk2(v.x, v.y);
            w2[gate][2 * q + 1] = pk2(v.z, v.w);
        }
    }

    float cst = (lane == 0) ? __ldg(c0 + j) : 0.f;
    const float nl_scale = (lane == 2) ? 2.f : 1.f;   // tanh lane via sig(2x)

    // This thread stages h elements k = tid*4 .. tid*4+3
    const int kbase = tid * 4;
    const int col   = tid >> 3;      // (tid*4+e)>>5 for e<4

    for (int t = 0; t < SEQ; t++) {
        // xg prefetch (independent of h): lanes 0..3 fetch this unit's gates
        float xr = 0.f;
        if (lane < 4)
            xr = __ldg(g_xg + (size_t)t * FH + lane * HID + j);

        if (t == 0) {
            float4 hv = *((const float4*)h0 + tid);
            sh[(kbase + 0) & 31][col] = hv.x;
            sh[(kbase + 1) & 31][col] = hv.y;
            sh[(kbase + 2) & 31][col] = hv.z;
            sh[(kbase + 3) & 31][col] = hv.w;
        } else {
            // Poll the tagged h pairs directly (tag == t means h_{t-1} ready)
            const unsigned long long* src = &g_hpair[(t - 1) & 1][kbase];
            unsigned int v0, g0, v1, g1, v2, g2, v3, g3;
            const unsigned int want = (unsigned int)t;
            do {
                asm volatile("ld.global.cg.v4.b32 {%0,%1,%2,%3}, [%4];"
                             : "=r"(v0), "=r"(g0), "=r"(v1), "=r"(g1)
                             : "l"(src));
                asm volatile("ld.global.cg.v4.b32 {%0,%1,%2,%3}, [%4];"
                             : "=r"(v2), "=r"(g2), "=r"(v3), "=r"(g3)
                             : "l"(src + 2));
            } while (g0 != want || g1 != want || g2 != want || g3 != want);
            sh[(kbase + 0) & 31][col] = __uint_as_float(v0);
            sh[(kbase + 1) & 31][col] = __uint_as_float(v1);
            sh[(kbase + 2) & 31][col] = __uint_as_float(v2);
            sh[(kbase + 3) & 31][col] = __uint_as_float(v3);
        }
        __syncthreads();

        // Mat-vec: thread covers k = lane*32 .. +31; h[lane*32+i] = sh[i][lane]
        unsigned long long a0 = pk2(0.f, 0.f), a1 = a0, a2 = a0, a3 = a0;
#pragma unroll
        for (int q = 0; q < 16; q++) {
            unsigned long long h2 = pk2(sh[2 * q][lane], sh[2 * q + 1][lane]);
            a0 = fma2(w2[0][q], h2, a0);
            a1 = fma2(w2[1][q], h2, a1);
            a2 = fma2(w2[2][q], h2, a2);
            a3 = fma2(w2[3][q], h2, a3);
        }
        float acc[4];
        { float x, y; upk2(a0, x, y); acc[0] = x + y;
          upk2(a1, x, y); acc[1] = x + y;
          upk2(a2, x, y); acc[2] = x + y;
          upk2(a3, x, y); acc[3] = x + y; }
#pragma unroll
        for (int off = 16; off >= 1; off >>= 1) {
            acc[0] += __shfl_xor_sync(0xffffffffu, acc[0], off);
            acc[1] += __shfl_xor_sync(0xffffffffu, acc[1], off);
            acc[2] += __shfl_xor_sync(0xffffffffu, acc[2], off);
            acc[3] += __shfl_xor_sync(0xffffffffu, acc[3], off);
        }

        // lanes 0..3 compute the four gate activations in parallel
        float act = 0.f;
        if (lane < 4) {
            float p = acc[lane] + xr;
            float s = 1.f / (1.f + __expf(-nl_scale * p));
            act = (lane == 2) ? (2.f * s - 1.f) : s;
        }
        float iv = __shfl_sync(0xffffffffu, act, 0);
        float fv = __shfl_sync(0xffffffffu, act, 1);
        float gv = __shfl_sync(0xffffffffu, act, 2);
        float ov = __shfl_sync(0xffffffffu, act, 3);
        if (lane == 0) {
            cst = fv * cst + iv * gv;
            float s2 = 1.f / (1.f + __expf(-2.f * cst));
            float hval = ov * (2.f * s2 - 1.f);
            unsigned long long pv =
                ((unsigned long long)(unsigned int)(t + 1) << 32) |
                (unsigned long long)__float_as_uint(hval);
            asm volatile("st.global.cg.u64 [%0], %1;"
                         :: "l"(&g_hpair[t & 1][j]), "l"(pv) : "memory");
        }
        __syncthreads();   // protect sh[] reuse (writers wait for readers)
    }
}

// ---------------------------------------------------------------------------
// Kernel C: clear tags so the captured graph replays deterministically.
// ---------------------------------------------------------------------------
__global__ __launch_bounds__(1024) void reset_tags_k() {
    g_hpair[0][threadIdx.x] = 0ull;
    g_hpair[1][threadIdx.x] = 0ull;
}

// ---------------------------------------------------------------------------
// Kernel D: out = log_softmax(h_final); h_final in g_hpair[(SEQ-1)&1] (low 32b)
// ---------------------------------------------------------------------------
__global__ __launch_bounds__(1024) void logsoftmax_k(float* __restrict__ out)
{
    __shared__ float red[32];
    __shared__ float s_m, s_s;
    const int tid = threadIdx.x;
    float x = __uint_as_float((unsigned int)(g_hpair[(SEQ - 1) & 1][tid]));

    float m = x;
#pragma unroll
    for (int off = 16; off >= 1; off >>= 1)
        m = fmaxf(m, __shfl_xor_sync(0xffffffffu, m, off));
    if ((tid & 31) == 0) red[tid >> 5] = m;
    __syncthreads();
    if (tid < 32) {
        float v = red[tid];
#pragma unroll
        for (int off = 16; off >= 1; off >>= 1)
            v = fmaxf(v, __shfl_xor_sync(0xffffffffu, v, off));
        if (tid == 0) s_m = v;
    }
    __syncthreads();

    float e = __expf(x - s_m);
    float s = e;
#pragma unroll
    for (int off = 16; off >= 1; off >>= 1)
        s += __shfl_xor_sync(0xffffffffu, s, off);
    if ((tid & 31) == 0) red[tid >> 5] = s;
    __syncthreads();
    if (tid < 32) {
        float v = red[tid];
#pragma unroll
        for (int off = 16; off >= 1; off >>= 1)
            v += __shfl_xor_sync(0xffffffffu, v, off);
        if (tid == 0) s_s = v;
    }
    __syncthreads();

    out[tid] = x - s_m - logf(s_s);
}

// ---------------------------------------------------------------------------
extern "C" void kernel_launch(void* const* d_in, const int* in_sizes, int n_in,
                              void* d_out, int out_size)
{
    const int*   tok = (const int*)  d_in[0];
    const float* emb = (const float*)d_in[1];
    const float* Wih = (const float*)d_in[2];
    const float* Whh = (const float*)d_in[3];
    const float* bih = (const float*)d_in[4];
    const float* bhh = (const float*)d_in[5];
    const float* h0  = (const float*)d_in[6];
    const float* c0  = (const float*)d_in[7];
    float* out = (float*)d_out;

    xg_gemm<<<dim3(FH / 128, SEQ / 128), 256>>>(tok, emb, Wih, bih, bhh);
    lstm_scan<<<NB, 256>>>(Whh, h0, c0);
    logsoftmax_k<<<1, 1024>>>(out);
    reset_tags_k<<<1, 1024>>>();   // after logsoftmax (it reads final h)
}